// round 3
// baseline (speedup 1.0000x reference)
#include <cuda_runtime.h>
#include <cstdint>
#include <cstddef>

#define NTOK 16384
#define DDIM 512
#define KCB  1024
#define NB   8

// ---------------- scratch (static device globals; no allocations) ----------
__device__ float  g_h  [NTOK * DDIM];   // 32MB  MLP temp
__device__ float  g_z  [NTOK * DDIM];   // 32MB  encoder output
__device__ float  g_zq [NTOK * DDIM];   // 32MB  quantized
__device__ float  g_dot[NTOK * KCB];    // 64MB  z @ codebook^T
__device__ float  g_enc[NTOK * KCB];    // 64MB  gumbel-softmax encodings
__device__ float  g_zz [NTOK];
__device__ float  g_cc [KCB];
__device__ float  g_avgp[KCB];
__device__ double g_kldd;
__device__ double g_kldc;

// ---------------- init: codebook row norms, zero accumulators --------------
__global__ void __launch_bounds__(256) init_kernel(const float* __restrict__ cb)
{
    int tid = threadIdx.x, lane = tid & 31, wid = tid >> 5;
    int gw = blockIdx.x * 8 + wid;                 // 256 warps total
    for (int r = gw; r < KCB; r += (int)gridDim.x * 8) {
        const float* p = cb + (size_t)r * DDIM;
        float s = 0.f;
        for (int i = lane; i < DDIM; i += 32) { float v = p[i]; s += v * v; }
        #pragma unroll
        for (int o = 16; o; o >>= 1) s += __shfl_xor_sync(0xffffffffu, s, o);
        if (!lane) g_cc[r] = s;
    }
    int g = blockIdx.x * blockDim.x + tid;
    if (g < KCB) g_avgp[g] = 0.f;
    if (g == 0) { g_kldd = 0.0; g_kldc = 0.0; }
}

// ---------------- fp32 tiled GEMM: C = op(A@B) --------------------------
// A: [M,K] row-major. TRANSB=0: B [K,N] row-major. TRANSB=1: B [N,K] row-major.
// BIASRELU: C = max(A@B + bias, 0). All dims multiples of tile sizes.
template<bool TRANSB, bool BIASRELU>
__global__ void __launch_bounds__(256) gemm_kernel(
    const float* __restrict__ A, const float* __restrict__ B,
    const float* __restrict__ bias, float* __restrict__ C,
    int M, int N, int K)
{
    __shared__ float As[2][8][128];
    __shared__ float Bs[2][8][128];
    const int tid  = threadIdx.x;
    const int tx   = tid & 15, ty = tid >> 4;
    const int row0 = blockIdx.y * 128;
    const int col0 = blockIdx.x * 128;

    const int aRow = tid >> 1;
    const int aK   = (tid & 1) << 2;
    const float* Aptr = A + (size_t)(row0 + aRow) * K + aK;

    const float* Bptr;
    int bRow = 0, bCol = 0;
    if (TRANSB) {
        Bptr = B + (size_t)(col0 + aRow) * K + aK;
    } else {
        bRow = tid >> 5;                // k index 0..7
        bCol = (tid & 31) << 2;         // col 0..124
        Bptr = B + (size_t)bRow * N + col0 + bCol;
    }

    float acc[8][8];
    #pragma unroll
    for (int i = 0; i < 8; i++)
        #pragma unroll
        for (int j = 0; j < 8; j++) acc[i][j] = 0.f;

    const int nk = K >> 3;

    // prologue: tile 0
    {
        float4 av = *reinterpret_cast<const float4*>(Aptr);
        As[0][aK + 0][aRow] = av.x; As[0][aK + 1][aRow] = av.y;
        As[0][aK + 2][aRow] = av.z; As[0][aK + 3][aRow] = av.w;
        if (TRANSB) {
            float4 bv = *reinterpret_cast<const float4*>(Bptr);
            Bs[0][aK + 0][aRow] = bv.x; Bs[0][aK + 1][aRow] = bv.y;
            Bs[0][aK + 2][aRow] = bv.z; Bs[0][aK + 3][aRow] = bv.w;
        } else {
            float4 bv = *reinterpret_cast<const float4*>(Bptr);
            *reinterpret_cast<float4*>(&Bs[0][bRow][bCol]) = bv;
        }
    }
    __syncthreads();

    for (int kt = 0; kt < nk; ++kt) {
        const int buf = kt & 1;
        float4 av, bv;
        if (kt + 1 < nk) {
            av = *reinterpret_cast<const float4*>(Aptr + (kt + 1) * 8);
            if (TRANSB) bv = *reinterpret_cast<const float4*>(Bptr + (kt + 1) * 8);
            else        bv = *reinterpret_cast<const float4*>(Bptr + (size_t)(kt + 1) * 8 * N);
        }
        #pragma unroll
        for (int kk = 0; kk < 8; kk++) {
            float4 a0 = *reinterpret_cast<const float4*>(&As[buf][kk][ty * 8]);
            float4 a1 = *reinterpret_cast<const float4*>(&As[buf][kk][ty * 8 + 4]);
            float4 b0 = *reinterpret_cast<const float4*>(&Bs[buf][kk][tx * 8]);
            float4 b1 = *reinterpret_cast<const float4*>(&Bs[buf][kk][tx * 8 + 4]);
            float a[8] = {a0.x, a0.y, a0.z, a0.w, a1.x, a1.y, a1.z, a1.w};
            float b[8] = {b0.x, b0.y, b0.z, b0.w, b1.x, b1.y, b1.z, b1.w};
            #pragma unroll
            for (int i = 0; i < 8; i++)
                #pragma unroll
                for (int j = 0; j < 8; j++)
                    acc[i][j] = fmaf(a[i], b[j], acc[i][j]);
        }
        if (kt + 1 < nk) {
            const int nb = buf ^ 1;
            As[nb][aK + 0][aRow] = av.x; As[nb][aK + 1][aRow] = av.y;
            As[nb][aK + 2][aRow] = av.z; As[nb][aK + 3][aRow] = av.w;
            if (TRANSB) {
                Bs[nb][aK + 0][aRow] = bv.x; Bs[nb][aK + 1][aRow] = bv.y;
                Bs[nb][aK + 2][aRow] = bv.z; Bs[nb][aK + 3][aRow] = bv.w;
            } else {
                *reinterpret_cast<float4*>(&Bs[nb][bRow][bCol]) = bv;
            }
        }
        __syncthreads();
    }

    float bvv[8];
    if (BIASRELU) {
        #pragma unroll
        for (int j = 0; j < 8; j++) bvv[j] = bias[col0 + tx * 8 + j];
    }
    #pragma unroll
    for (int i = 0; i < 8; i++) {
        float v[8];
        #pragma unroll
        for (int j = 0; j < 8; j++) {
            float t = acc[i][j];
            if (BIASRELU) t = fmaxf(t + bvv[j], 0.f);
            v[j] = t;
        }
        float* cp = C + (size_t)(row0 + ty * 8 + i) * N + col0 + tx * 8;
        *reinterpret_cast<float4*>(cp)     = make_float4(v[0], v[1], v[2], v[3]);
        *reinterpret_cast<float4*>(cp + 4) = make_float4(v[4], v[5], v[6], v[7]);
    }
}

// ---------------- per-row LayerNorm (row length 512) -----------------------
__global__ void __launch_bounds__(256) ln_kernel(
    const float* __restrict__ in, const float* __restrict__ g,
    const float* __restrict__ be, float* __restrict__ out,
    float* __restrict__ zz)
{
    __shared__ float red[256];
    const int row = blockIdx.x, tid = threadIdx.x;
    const float* p = in + (size_t)row * DDIM;
    float x0 = p[tid], x1 = p[tid + 256];

    red[tid] = x0 + x1; __syncthreads();
    #pragma unroll
    for (int o = 128; o; o >>= 1) { if (tid < o) red[tid] += red[tid + o]; __syncthreads(); }
    float mean = red[0] * (1.f / DDIM); __syncthreads();

    float d0 = x0 - mean, d1 = x1 - mean;
    red[tid] = d0 * d0 + d1 * d1; __syncthreads();
    #pragma unroll
    for (int o = 128; o; o >>= 1) { if (tid < o) red[tid] += red[tid + o]; __syncthreads(); }
    float rstd = rsqrtf(red[0] * (1.f / DDIM) + 1e-5f); __syncthreads();

    float y0 = d0 * rstd * g[tid]       + be[tid];
    float y1 = d1 * rstd * g[tid + 256] + be[tid + 256];
    float* q = out + (size_t)row * DDIM;
    q[tid] = y0; q[tid + 256] = y1;

    if (zz) {
        red[tid] = y0 * y0 + y1 * y1; __syncthreads();
        #pragma unroll
        for (int o = 128; o; o >>= 1) { if (tid < o) red[tid] += red[tid + o]; __syncthreads(); }
        if (!tid) zz[row] = red[0];
    }
}

// ---------------- quantizer: logits, log-softmax stats, gumbel-softmax -----
// warp-per-row; 8 warps/block, 64 rows/block, grid = 256 blocks
__global__ void __launch_bounds__(256) quant_kernel(
    const float* __restrict__ gum, const float* __restrict__ lpq)
{
    __shared__ float s_cc[KCB];
    __shared__ float s_avg[8][KCB];     // per-warp avg_probs slices (32KB)
    const int tid = threadIdx.x, lane = tid & 31, wid = tid >> 5;
    const float w = 0.5f / fmaxf(__expf(lpq[0]), 1e-10f);

    for (int j = tid; j < KCB; j += 256) s_cc[j] = g_cc[j];
    for (int j = tid; j < 8 * KCB; j += 256) (&s_avg[0][0])[j] = 0.f;
    __syncthreads();

    double kd = 0.0;
    const int row0 = blockIdx.x * 64;
    for (int r = wid; r < 64; r += 8) {
        const int row = row0 + r;
        const float* dp = g_dot + (size_t)row * KCB;
        const float* up = gum   + (size_t)row * KCB;
        const float zzr = g_zz[row];

        float lg[32];
        float mx = -1e30f;
        #pragma unroll
        for (int q = 0; q < 32; q++) {
            int j = lane + (q << 5);
            float l = w * (2.f * dp[j] - zzr - s_cc[j]);
            lg[q] = l;
            mx = fmaxf(mx, l);
        }
        #pragma unroll
        for (int o = 16; o; o >>= 1) mx = fmaxf(mx, __shfl_xor_sync(0xffffffffu, mx, o));

        float se = 0.f;
        #pragma unroll
        for (int q = 0; q < 32; q++) se += __expf(lg[q] - mx);
        #pragma unroll
        for (int o = 16; o; o >>= 1) se += __shfl_xor_sync(0xffffffffu, se, o);
        const float lse = __logf(se);

        float pd = 0.f;
        #pragma unroll
        for (int q = 0; q < 32; q++) {
            int j = lane + (q << 5);
            float lp = lg[q] - mx - lse;
            float p = __expf(lp);
            pd += p * lp;
            s_avg[wid][j] += p;
        }
        #pragma unroll
        for (int o = 16; o; o >>= 1) pd += __shfl_xor_sync(0xffffffffu, pd, o);
        if (!lane) kd += (double)pd;

        // gumbel-softmax encodings
        float mx2 = -1e30f;
        #pragma unroll
        for (int q = 0; q < 32; q++) {
            int j = lane + (q << 5);
            float u = up[j];
            float gn = -__logf(-__logf(u + 1e-10f) + 1e-10f);
            float a = lg[q] + gn;
            lg[q] = a;
            mx2 = fmaxf(mx2, a);
        }
        #pragma unroll
        for (int o = 16; o; o >>= 1) mx2 = fmaxf(mx2, __shfl_xor_sync(0xffffffffu, mx2, o));

        float s2 = 0.f;
        #pragma unroll
        for (int q = 0; q < 32; q++) { float e = __expf(lg[q] - mx2); lg[q] = e; s2 += e; }
        #pragma unroll
        for (int o = 16; o; o >>= 1) s2 += __shfl_xor_sync(0xffffffffu, s2, o);
        const float inv = 1.f / s2;

        float* ep = g_enc + (size_t)row * KCB;
        #pragma unroll
        for (int q = 0; q < 32; q++) ep[lane + (q << 5)] = lg[q] * inv;
    }
    __syncthreads();

    for (int j = tid; j < KCB; j += 256) {
        float s = 0.f;
        #pragma unroll
        for (int ww = 0; ww < 8; ww++) s += s_avg[ww][j];
        atomicAdd(&g_avgp[j], s);
    }
    if (!lane) atomicAdd(&g_kldd, kd);
}

// ---------------- sum((z - z_q)^2) ------------------------------------------
__global__ void __launch_bounds__(256) sq_kernel()
{
    size_t gid = (size_t)blockIdx.x * 256 + threadIdx.x;
    size_t stride = (size_t)gridDim.x * 256;
    float acc = 0.f;
    for (size_t i = gid; i < (size_t)NTOK * DDIM; i += stride) {
        float d = g_z[i] - g_zq[i];
        acc += d * d;
    }
    #pragma unroll
    for (int o = 16; o; o >>= 1) acc += __shfl_xor_sync(0xffffffffu, acc, o);
    __shared__ double sred[8];
    int lane = threadIdx.x & 31, wid = threadIdx.x >> 5;
    if (!lane) sred[wid] = (double)acc;
    __syncthreads();
    if (threadIdx.x == 0) {
        double s = 0.0;
        #pragma unroll
        for (int i = 0; i < 8; i++) s += sred[i];
        atomicAdd(&g_kldc, s);
    }
}

// ---------------- finalize: loss + perplexity --------------------------------
__global__ void __launch_bounds__(256) fin_kernel(
    const float* __restrict__ lpq, float* __restrict__ out)
{
    __shared__ double red[256];
    const int tid = threadIdx.x;
    double h = 0.0;
    for (int j = tid; j < KCB; j += 256) {
        float a = g_avgp[j] * (1.f / NTOK);
        h += (double)(a * __logf(a + 1e-7f));
    }
    red[tid] = h; __syncthreads();
    #pragma unroll
    for (int o = 128; o; o >>= 1) { if (tid < o) red[tid] += red[tid + o]; __syncthreads(); }
    if (!tid) {
        float w = 0.5f / fmaxf(__expf(lpq[0]), 1e-10f);
        double loss = g_kldd / (double)NB + g_kldc * (double)w / (double)NB;
        out[(size_t)NTOK * DDIM]     = (float)loss;
        out[(size_t)NTOK * DDIM + 1] = __expf((float)(-red[0]));
    }
}

// ---------------- launch ----------------------------------------------------
extern "C" void kernel_launch(void* const* d_in, const int* in_sizes, int n_in,
                              void* d_out, int out_size)
{
    (void)in_sizes; (void)n_in; (void)out_size;
    const float* x    = (const float*)d_in[0];
    const float* gum  = (const float*)d_in[1];
    const float* ew1  = (const float*)d_in[2];  const float* eb1  = (const float*)d_in[3];
    const float* eg1  = (const float*)d_in[4];  const float* ebe1 = (const float*)d_in[5];
    const float* ew2  = (const float*)d_in[6];  const float* eb2  = (const float*)d_in[7];
    const float* eg2  = (const float*)d_in[8];  const float* ebe2 = (const float*)d_in[9];
    const float* dw1  = (const float*)d_in[10]; const float* db1  = (const float*)d_in[11];
    const float* dg1  = (const float*)d_in[12]; const float* dbe1 = (const float*)d_in[13];
    const float* dw2  = (const float*)d_in[14]; const float* db2  = (const float*)d_in[15];
    const float* dg2  = (const float*)d_in[16]; const float* dbe2 = (const float*)d_in[17];
    const float* cb   = (const float*)d_in[18];
    const float* lpq  = (const float*)d_in[19];
    float* out = (float*)d_out;

    float *p_h, *p_z, *p_zq, *p_dot, *p_enc, *p_zz;
    cudaGetSymbolAddress((void**)&p_h,   g_h);
    cudaGetSymbolAddress((void**)&p_z,   g_z);
    cudaGetSymbolAddress((void**)&p_zq,  g_zq);
    cudaGetSymbolAddress((void**)&p_dot, g_dot);
    cudaGetSymbolAddress((void**)&p_enc, g_enc);
    cudaGetSymbolAddress((void**)&p_zz,  g_zz);

    dim3 gD(DDIM / 128, NTOK / 128);   // (4, 128)
    dim3 gK(KCB  / 128, NTOK / 128);   // (8, 128)

    init_kernel<<<32, 256>>>(cb);

    // encoder
    gemm_kernel<false, true ><<<gD, 256>>>(x,   ew1, eb1, p_h, NTOK, DDIM, DDIM);
    ln_kernel<<<NTOK, 256>>>(p_h, eg1, ebe1, p_h, nullptr);
    gemm_kernel<false, true ><<<gD, 256>>>(p_h, ew2, eb2, p_z, NTOK, DDIM, DDIM);
    ln_kernel<<<NTOK, 256>>>(p_z, eg2, ebe2, p_z, p_zz);

    // quantizer
    gemm_kernel<true,  false><<<gK, 256>>>(p_z, cb, nullptr, p_dot, NTOK, KCB, DDIM);
    quant_kernel<<<256, 256>>>(gum, lpq);
    gemm_kernel<false, false><<<gD, 256>>>(p_enc, cb, nullptr, p_zq, NTOK, DDIM, KCB);
    sq_kernel<<<512, 256>>>();

    // decoder (final LN writes directly into d_out)
    gemm_kernel<false, true ><<<gD, 256>>>(p_zq, dw1, db1, p_h, NTOK, DDIM, DDIM);
    ln_kernel<<<NTOK, 256>>>(p_h, dg1, dbe1, p_h, nullptr);
    gemm_kernel<false, true ><<<gD, 256>>>(p_h, dw2, db2, out, NTOK, DDIM, DDIM);
    ln_kernel<<<NTOK, 256>>>(out, dg2, dbe2, out, nullptr);

    fin_kernel<<<1, 256>>>(lpq, out);
}

// round 5
// speedup vs baseline: 2.3300x; 2.3300x over previous
#include <cuda_runtime.h>
#include <cuda_bf16.h>
#include <cstdint>
#include <cstddef>

#define NTOK 16384
#define DDIM 512
#define KCB  1024
#define NB   8

// ---------------- scratch (static device globals; no allocations) ----------
__device__ float g_h  [NTOK * DDIM];    // pre-LN MLP temp
__device__ float g_z  [NTOK * DDIM];    // encoder output (post-LN)
__device__ float g_zq [NTOK * DDIM];    // quantized
__device__ float g_dot[NTOK * KCB];     // z @ codebook^T
__device__ __align__(128) __nv_bfloat16 g_ah[NTOK * KCB];   // A-side split hi
__device__ __align__(128) __nv_bfloat16 g_al[NTOK * KCB];   // A-side split lo
__device__ __align__(128) __nv_bfloat16 g_wh[4 * DDIM * DDIM]; // transposed weights hi
__device__ __align__(128) __nv_bfloat16 g_wl[4 * DDIM * DDIM];
__device__ __align__(128) __nv_bfloat16 g_cbh [KCB * DDIM];    // codebook split
__device__ __align__(128) __nv_bfloat16 g_cbl [KCB * DDIM];
__device__ __align__(128) __nv_bfloat16 g_cbth[DDIM * KCB];    // codebook^T split
__device__ __align__(128) __nv_bfloat16 g_cbtl[DDIM * KCB];
__device__ float  g_zz [NTOK];
__device__ float  g_cc [KCB];
__device__ float  g_avgp[KCB];
__device__ double g_kldd;
__device__ double g_kldc;

// ---------------- PTX helpers ----------------------------------------------
__device__ __forceinline__ uint32_t smem_u32(const void* p) {
    uint32_t a;
    asm("{ .reg .u64 t; cvta.to.shared.u64 t, %1; cvt.u32.u64 %0, t; }"
        : "=r"(a) : "l"(p));
    return a;
}

#define CP_ASYNC16(s, g) \
    asm volatile("cp.async.cg.shared.global [%0], [%1], 16;" :: "r"(s), "l"(g))
#define CP_COMMIT() asm volatile("cp.async.commit_group;" ::: "memory")
#define CP_WAIT(n)  asm volatile("cp.async.wait_group %0;" :: "n"(n) : "memory")

#define LDSM4(r, addr) \
    asm volatile("ldmatrix.sync.aligned.m8n8.x4.shared.b16 {%0,%1,%2,%3}, [%4];" \
        : "=r"((r)[0]), "=r"((r)[1]), "=r"((r)[2]), "=r"((r)[3]) : "r"(addr) : "memory")

#define MMA_BF16(D, A, B0, B1) \
    asm volatile("mma.sync.aligned.m16n8k16.row.col.f32.bf16.bf16.f32 " \
        "{%0,%1,%2,%3}, {%4,%5,%6,%7}, {%8,%9}, {%0,%1,%2,%3};" \
        : "+f"((D)[0]), "+f"((D)[1]), "+f"((D)[2]), "+f"((D)[3]) \
        : "r"((A)[0]), "r"((A)[1]), "r"((A)[2]), "r"((A)[3]), "r"(B0), "r"(B1))

__device__ __forceinline__ uint32_t sw128(uint32_t off) {
    return off ^ ((off >> 3) & 0x70);
}

// ---------------- tile loader: 128 rows x 64 bf16 cols, SW128 swizzled ------
__device__ __forceinline__ void load_tile(uint32_t tb, const __nv_bfloat16* __restrict__ src,
                                          int r0, int k0, int K, int tid)
{
    #pragma unroll
    for (int i = 0; i < 4; i++) {
        int u = tid + (i << 8);
        int row = u >> 3, col8 = (u & 7) << 3;
        const __nv_bfloat16* gp = src + (size_t)(r0 + row) * K + k0 + col8;
        uint32_t off = (uint32_t)((row << 7) + (col8 << 1));
        CP_ASYNC16(tb + sw128(off), gp);
    }
}

// ---------------- mma.sync bf16x3 GEMM: C = (Ah+Al)@(Bh+Bl)^T ---------------
// A: [M,K] (hi/lo bf16). B: [N,K] (hi/lo bf16, row-major = pre-transposed).
// C fp32 [M,N]. BIASRELU: C = max(C + bias, 0).
#define SMEM_STAGE 65536
#define SMEM_GEMM  (2 * SMEM_STAGE)

template<bool BIASRELU>
__global__ void __launch_bounds__(256, 1) mma_gemm(
    const __nv_bfloat16* __restrict__ Ah, const __nv_bfloat16* __restrict__ Al,
    const __nv_bfloat16* __restrict__ Bh, const __nv_bfloat16* __restrict__ Bl,
    const float* __restrict__ bias, float* __restrict__ C,
    int M, int N, int K)
{
    extern __shared__ char smem[];
    const int tid  = threadIdx.x;
    const int wid  = tid >> 5, lane = tid & 31;
    const int wm   = wid & 1, wn = wid >> 1;      // 2x4 warp grid: 64x32 per warp
    const uint32_t sb = smem_u32(smem);

    const int row0 = blockIdx.y << 7, col0 = blockIdx.x << 7;
    const int nk = K >> 6;

    float acc[4][4][4];
    #pragma unroll
    for (int i = 0; i < 4; i++)
        #pragma unroll
        for (int j = 0; j < 4; j++)
            #pragma unroll
            for (int r = 0; r < 4; r++) acc[i][j][r] = 0.f;

    // per-lane ldmatrix offset bases (within a 128x64 bf16 tile, 128B rows)
    // A: row = mtbase + (lane & 15), kbyte = (lane>>4)*16
    const uint32_t a_row  = (uint32_t)(lane & 15);
    const uint32_t a_koff = (uint32_t)((lane >> 4) << 4);
    // B: nrow = npbase + ((lane>>4)<<3) + (lane&7), kbyte = ((lane>>3)&1)*16
    const uint32_t b_row  = (uint32_t)(((lane >> 4) << 3) + (lane & 7));
    const uint32_t b_koff = (uint32_t)(((lane >> 3) & 1) << 4);

    // prologue: stage 0
    load_tile(sb + 0,     Ah, row0, 0, K, tid);
    load_tile(sb + 16384, Al, row0, 0, K, tid);
    load_tile(sb + 32768, Bh, col0, 0, K, tid);
    load_tile(sb + 49152, Bl, col0, 0, K, tid);
    CP_COMMIT();

    for (int kt = 0; kt < nk; kt++) {
        const int b = kt & 1;
        if (kt + 1 < nk) {
            const int k0 = (kt + 1) << 6;
            const uint32_t st = sb + (b ^ 1) * SMEM_STAGE;
            load_tile(st + 0,     Ah, row0, k0, K, tid);
            load_tile(st + 16384, Al, row0, k0, K, tid);
            load_tile(st + 32768, Bh, col0, k0, K, tid);
            load_tile(st + 49152, Bl, col0, k0, K, tid);
            CP_COMMIT();
            CP_WAIT(1);
        } else {
            CP_WAIT(0);
        }
        __syncthreads();

        const uint32_t stA_h = sb + b * SMEM_STAGE;
        const uint32_t stA_l = stA_h + 16384;
        const uint32_t stB_h = stA_h + 32768;
        const uint32_t stB_l = stA_h + 49152;

        #pragma unroll
        for (int ks = 0; ks < 4; ks++) {
            const uint32_t k0b = (uint32_t)(ks << 5);   // 16 elems = 32 bytes
            uint32_t ah[4][4], al[4][4];
            #pragma unroll
            for (int mt = 0; mt < 4; mt++) {
                uint32_t off = ((uint32_t)(wm * 64 + mt * 16) + a_row) * 128 + k0b + a_koff;
                uint32_t s = sw128(off);
                LDSM4(ah[mt], stA_h + s);
                LDSM4(al[mt], stA_l + s);
            }
            uint32_t bh[2][4], bl[2][4];
            #pragma unroll
            for (int np = 0; np < 2; np++) {
                uint32_t off = ((uint32_t)(wn * 32 + np * 16) + b_row) * 128 + k0b + b_koff;
                uint32_t s = sw128(off);
                LDSM4(bh[np], stB_h + s);
                LDSM4(bl[np], stB_l + s);
            }
            #pragma unroll
            for (int mt = 0; mt < 4; mt++) {
                #pragma unroll
                for (int nt = 0; nt < 4; nt++) {
                    const int np = nt >> 1, pr = (nt & 1) << 1;
                    MMA_BF16(acc[mt][nt], ah[mt], bh[np][pr], bh[np][pr + 1]);
                    MMA_BF16(acc[mt][nt], ah[mt], bl[np][pr], bl[np][pr + 1]);
                    MMA_BF16(acc[mt][nt], al[mt], bh[np][pr], bh[np][pr + 1]);
                }
            }
        }
        __syncthreads();
    }

    // epilogue: fragment layout d0,d1 -> (row = lane>>2, col = 2*(lane&3)), d2,d3 -> row+8
    const int erow = row0 + wm * 64 + (lane >> 2);
    const int ecol = col0 + wn * 32 + ((lane & 3) << 1);
    #pragma unroll
    for (int mt = 0; mt < 4; mt++) {
        #pragma unroll
        for (int nt = 0; nt < 4; nt++) {
            const int r0 = erow + mt * 16;
            const int c  = ecol + nt * 8;
            float v0 = acc[mt][nt][0], v1 = acc[mt][nt][1];
            float v2 = acc[mt][nt][2], v3 = acc[mt][nt][3];
            if (BIASRELU) {
                float b0 = bias[c], b1 = bias[c + 1];
                v0 = fmaxf(v0 + b0, 0.f); v1 = fmaxf(v1 + b1, 0.f);
                v2 = fmaxf(v2 + b0, 0.f); v3 = fmaxf(v3 + b1, 0.f);
            }
            *reinterpret_cast<float2*>(C + (size_t)r0 * N + c)       = make_float2(v0, v1);
            *reinterpret_cast<float2*>(C + (size_t)(r0 + 8) * N + c) = make_float2(v2, v3);
        }
    }
}

// ---------------- split fp32 -> (hi, lo) bf16 --------------------------------
__global__ void __launch_bounds__(256) split_kernel(
    const float* __restrict__ src,
    __nv_bfloat16* __restrict__ oh, __nv_bfloat16* __restrict__ ol, int n)
{
    int i = blockIdx.x * 256 + threadIdx.x;
    int stride = gridDim.x * 256;
    for (; i < n; i += stride) {
        float v = src[i];
        __nv_bfloat16 h = __float2bfloat16(v);
        oh[i] = h;
        ol[i] = __float2bfloat16(v - __bfloat162float(h));
    }
}

// ---------------- transpose + split: in [R,C] fp32 -> out [C,R] hi/lo bf16 ---
__global__ void __launch_bounds__(256) tsp_kernel(
    const float* __restrict__ in,
    __nv_bfloat16* __restrict__ oh, __nv_bfloat16* __restrict__ ol, int R, int C)
{
    __shared__ float t[32][33];
    const int bx = blockIdx.x, by = blockIdx.y;
    const int txx = threadIdx.x, tyy = threadIdx.y;  // block (32, 8)
    #pragma unroll
    for (int i = tyy; i < 32; i += 8)
        t[i][txx] = in[(size_t)(by * 32 + i) * C + bx * 32 + txx];
    __syncthreads();
    #pragma unroll
    for (int i = tyy; i < 32; i += 8) {
        float v = t[txx][i];
        size_t o = (size_t)(bx * 32 + i) * R + by * 32 + txx;
        __nv_bfloat16 h = __float2bfloat16(v);
        oh[o] = h;
        ol[o] = __float2bfloat16(v - __bfloat162float(h));
    }
}

// ---------------- init: codebook row norms, zero accumulators ---------------
__global__ void __launch_bounds__(256) init_kernel(const float* __restrict__ cb)
{
    int tid = threadIdx.x, lane = tid & 31, wid = tid >> 5;
    int gw = blockIdx.x * 8 + wid;
    for (int r = gw; r < KCB; r += (int)gridDim.x * 8) {
        const float* p = cb + (size_t)r * DDIM;
        float s = 0.f;
        for (int i = lane; i < DDIM; i += 32) { float v = p[i]; s += v * v; }
        #pragma unroll
        for (int o = 16; o; o >>= 1) s += __shfl_xor_sync(0xffffffffu, s, o);
        if (!lane) g_cc[r] = s;
    }
    int g = blockIdx.x * blockDim.x + tid;
    if (g < KCB) g_avgp[g] = 0.f;
    if (g == 0) { g_kldd = 0.0; g_kldc = 0.0; }
}

// ---------------- LayerNorm (row 512) + optional fp32 out + bf16 splits ------
__global__ void __launch_bounds__(256) ln_kernel(
    const float* __restrict__ in, const float* __restrict__ g,
    const float* __restrict__ be, float* __restrict__ out,
    __nv_bfloat16* __restrict__ oh, __nv_bfloat16* __restrict__ ol,
    float* __restrict__ zz)
{
    __shared__ float red[256];
    const int row = blockIdx.x, tid = threadIdx.x;
    const float* p = in + (size_t)row * DDIM;
    float x0 = p[tid], x1 = p[tid + 256];

    red[tid] = x0 + x1; __syncthreads();
    #pragma unroll
    for (int o = 128; o; o >>= 1) { if (tid < o) red[tid] += red[tid + o]; __syncthreads(); }
    float mean = red[0] * (1.f / DDIM); __syncthreads();

    float d0 = x0 - mean, d1 = x1 - mean;
    red[tid] = d0 * d0 + d1 * d1; __syncthreads();
    #pragma unroll
    for (int o = 128; o; o >>= 1) { if (tid < o) red[tid] += red[tid + o]; __syncthreads(); }
    float rstd = rsqrtf(red[0] * (1.f / DDIM) + 1e-5f); __syncthreads();

    float y0 = d0 * rstd * g[tid]       + be[tid];
    float y1 = d1 * rstd * g[tid + 256] + be[tid + 256];
    if (out) {
        float* q = out + (size_t)row * DDIM;
        q[tid] = y0; q[tid + 256] = y1;
    }
    if (oh) {
        size_t b = (size_t)row * DDIM;
        __nv_bfloat16 h0 = __float2bfloat16(y0);
        __nv_bfloat16 h1 = __float2bfloat16(y1);
        oh[b + tid]       = h0; ol[b + tid]       = __float2bfloat16(y0 - __bfloat162float(h0));
        oh[b + tid + 256] = h1; ol[b + tid + 256] = __float2bfloat16(y1 - __bfloat162float(h1));
    }
    if (zz) {
        red[tid] = y0 * y0 + y1 * y1; __syncthreads();
        #pragma unroll
        for (int o = 128; o; o >>= 1) { if (tid < o) red[tid] += red[tid + o]; __syncthreads(); }
        if (!tid) zz[row] = red[0];
    }
}

// ---------------- quantizer: writes encodings as bf16 splits -----------------
__global__ void __launch_bounds__(256) quant_kernel(
    const float* __restrict__ gum, const float* __restrict__ lpq)
{
    __shared__ float s_cc[KCB];
    __shared__ float s_avg[8][KCB];
    const int tid = threadIdx.x, lane = tid & 31, wid = tid >> 5;
    const float w = 0.5f / fmaxf(__expf(lpq[0]), 1e-10f);

    for (int j = tid; j < KCB; j += 256) s_cc[j] = g_cc[j];
    for (int j = tid; j < 8 * KCB; j += 256) (&s_avg[0][0])[j] = 0.f;
    __syncthreads();

    double kd = 0.0;
    const int row0 = blockIdx.x * 64;
    for (int r = wid; r < 64; r += 8) {
        const int row = row0 + r;
        const float* dp = g_dot + (size_t)row * KCB;
        const float* up = gum   + (size_t)row * KCB;
        const float zzr = g_zz[row];

        float lg[32];
        float mx = -1e30f;
        #pragma unroll
        for (int q = 0; q < 32; q++) {
            int j = lane + (q << 5);
            float l = w * (2.f * dp[j] - zzr - s_cc[j]);
            lg[q] = l;
            mx = fmaxf(mx, l);
        }
        #pragma unroll
        for (int o = 16; o; o >>= 1) mx = fmaxf(mx, __shfl_xor_sync(0xffffffffu, mx, o));

        float se = 0.f;
        #pragma unroll
        for (int q = 0; q < 32; q++) se += __expf(lg[q] - mx);
        #pragma unroll
        for (int o = 16; o; o >>= 1) se += __shfl_xor_sync(0xffffffffu, se, o);
        const float lse = __logf(se);

        float pd = 0.f;
        #pragma unroll
        for (int q = 0; q < 32; q++) {
            int j = lane + (q << 5);
            float lp = lg[q] - mx - lse;
            float p = __expf(lp);
            pd += p * lp;
            s_avg[wid][j] += p;
        }
        #pragma unroll
        for (int o = 16; o; o >>= 1) pd += __shfl_xor_sync(0xffffffffu, pd, o);
        if (!lane) kd += (double)pd;

        float mx2 = -1e30f;
        #pragma unroll
        for (int q = 0; q < 32; q++) {
            int j = lane + (q << 5);
            float u = up[j];
            float gn = -__logf(-__logf(u + 1e-10f) + 1e-10f);
            float a = lg[q] + gn;
            lg[q] = a;
            mx2 = fmaxf(mx2, a);
        }
        #pragma unroll
        for (int o = 16; o; o >>= 1) mx2 = fmaxf(mx2, __shfl_xor_sync(0xffffffffu, mx2, o));

        float s2 = 0.f;
        #pragma unroll
        for (int q = 0; q < 32; q++) { float e = __expf(lg[q] - mx2); lg[q] = e; s2 += e; }
        #pragma unroll
        for (int o = 16; o; o >>= 1) s2 += __shfl_xor_sync(0xffffffffu, s2, o);
        const float inv = 1.f / s2;

        __nv_bfloat16* eph = g_ah + (size_t)row * KCB;
        __nv_bfloat16* epl = g_al + (size_t)row * KCB;
        #pragma unroll
        for (int q = 0; q < 32; q++) {
            int j = lane + (q << 5);
            float e = lg[q] * inv;
            __nv_bfloat16 h = __float2bfloat16(e);
            eph[j] = h;
            epl[j] = __float2bfloat16(e - __bfloat162float(h));
        }
    }
    __syncthreads();

    for (int j = tid; j < KCB; j += 256) {
        float s = 0.f;
        #pragma unroll
        for (int ww = 0; ww < 8; ww++) s += s_avg[ww][j];
        atomicAdd(&g_avgp[j], s);
    }
    if (!lane) atomicAdd(&g_kldd, kd);
}

// ---------------- sum((z - z_q)^2) + split z_q for decoder -------------------
__global__ void __launch_bounds__(256) sq_kernel()
{
    size_t gid = (size_t)blockIdx.x * 256 + threadIdx.x;
    size_t stride = (size_t)gridDim.x * 256;
    float acc = 0.f;
    for (size_t i = gid; i < (size_t)NTOK * DDIM; i += stride) {
        float qv = g_zq[i];
        float d = g_z[i] - qv;
        acc += d * d;
        __nv_bfloat16 h = __float2bfloat16(qv);
        g_ah[i] = h;
        g_al[i] = __float2bfloat16(qv - __bfloat162float(h));
    }
    #pragma unroll
    for (int o = 16; o; o >>= 1) acc += __shfl_xor_sync(0xffffffffu, acc, o);
    __shared__ double sred[8];
    int lane = threadIdx.x & 31, wid = threadIdx.x >> 5;
    if (!lane) sred[wid] = (double)acc;
    __syncthreads();
    if (threadIdx.x == 0) {
        double s = 0.0;
        #pragma unroll
        for (int i = 0; i < 8; i++) s += sred[i];
        atomicAdd(&g_kldc, s);
    }
}

// ---------------- finalize ----------------------------------------------------
__global__ void __launch_bounds__(256) fin_kernel(
    const float* __restrict__ lpq, float* __restrict__ out)
{
    __shared__ double red[256];
    const int tid = threadIdx.x;
    double h = 0.0;
    for (int j = tid; j < KCB; j += 256) {
        float a = g_avgp[j] * (1.f / NTOK);
        h += (double)(a * __logf(a + 1e-7f));
    }
    red[tid] = h; __syncthreads();
    #pragma unroll
    for (int o = 128; o; o >>= 1) { if (tid < o) red[tid] += red[tid + o]; __syncthreads(); }
    if (!tid) {
        float w = 0.5f / fmaxf(__expf(lpq[0]), 1e-10f);
        double loss = g_kldd / (double)NB + g_kldc * (double)w / (double)NB;
        out[(size_t)NTOK * DDIM]     = (float)loss;
        out[(size_t)NTOK * DDIM + 1] = __expf((float)(-red[0]));
    }
}

// ---------------- launch ------------------------------------------------------
extern "C" void kernel_launch(void* const* d_in, const int* in_sizes, int n_in,
                              void* d_out, int out_size)
{
    (void)in_sizes; (void)n_in; (void)out_size;
    const float* x    = (const float*)d_in[0];
    const float* gum  = (const float*)d_in[1];
    const float* ew1  = (const float*)d_in[2];  const float* eb1  = (const float*)d_in[3];
    const float* eg1  = (const float*)d_in[4];  const float* ebe1 = (const float*)d_in[5];
    const float* ew2  = (const float*)d_in[6];  const float* eb2  = (const float*)d_in[7];
    const float* eg2  = (const float*)d_in[8];  const float* ebe2 = (const float*)d_in[9];
    const float* dw1  = (const float*)d_in[10]; const float* db1  = (const float*)d_in[11];
    const float* dg1  = (const float*)d_in[12]; const float* dbe1 = (const float*)d_in[13];
    const float* dw2  = (const float*)d_in[14]; const float* db2  = (const float*)d_in[15];
    const float* dg2  = (const float*)d_in[16]; const float* dbe2 = (const float*)d_in[17];
    const float* cb   = (const float*)d_in[18];
    const float* lpq  = (const float*)d_in[19];
    float* out = (float*)d_out;

    float *p_h, *p_z, *p_zq, *p_dot, *p_zz;
    __nv_bfloat16 *p_ah, *p_al, *p_wh, *p_wl, *p_cbh, *p_cbl, *p_cbth, *p_cbtl;
    cudaGetSymbolAddress((void**)&p_h,    g_h);
    cudaGetSymbolAddress((void**)&p_z,    g_z);
    cudaGetSymbolAddress((void**)&p_zq,   g_zq);
    cudaGetSymbolAddress((void**)&p_dot,  g_dot);
    cudaGetSymbolAddress((void**)&p_zz,   g_zz);
    cudaGetSymbolAddress((void**)&p_ah,   g_ah);
    cudaGetSymbolAddress((void**)&p_al,   g_al);
    cudaGetSymbolAddress((void**)&p_wh,   g_wh);
    cudaGetSymbolAddress((void**)&p_wl,   g_wl);
    cudaGetSymbolAddress((void**)&p_cbh,  g_cbh);
    cudaGetSymbolAddress((void**)&p_cbl,  g_cbl);
    cudaGetSymbolAddress((void**)&p_cbth, g_cbth);
    cudaGetSymbolAddress((void**)&p_cbtl, g_cbtl);

    cudaFuncSetAttribute(mma_gemm<true>,  cudaFuncAttributeMaxDynamicSharedMemorySize, SMEM_GEMM);
    cudaFuncSetAttribute(mma_gemm<false>, cudaFuncAttributeMaxDynamicSharedMemorySize, SMEM_GEMM);

    const int WSZ = DDIM * DDIM;
    dim3 gD(DDIM / 128, NTOK / 128);   // (4, 128)
    dim3 gK(KCB  / 128, NTOK / 128);   // (8, 128)
    dim3 tspB(32, 8);

    // prep
    init_kernel<<<32, 256>>>(cb);
    split_kernel<<<4096, 256>>>(x, p_ah, p_al, NTOK * DDIM);
    tsp_kernel<<<dim3(16, 16), tspB>>>(ew1, p_wh + 0 * WSZ, p_wl + 0 * WSZ, DDIM, DDIM);
    tsp_kernel<<<dim3(16, 16), tspB>>>(ew2, p_wh + 1 * WSZ, p_wl + 1 * WSZ, DDIM, DDIM);
    tsp_kernel<<<dim3(16, 16), tspB>>>(dw1, p_wh + 2 * WSZ, p_wl + 2 * WSZ, DDIM, DDIM);
    tsp_kernel<<<dim3(16, 16), tspB>>>(dw2, p_wh + 3 * WSZ, p_wl + 3 * WSZ, DDIM, DDIM);
    tsp_kernel<<<dim3(16, 32), tspB>>>(cb, p_cbth, p_cbtl, KCB, DDIM);   // cb^T [512,1024]
    split_kernel<<<2048, 256>>>(cb, p_cbh, p_cbl, KCB * DDIM);

    // encoder
    mma_gemm<true ><<<gD, 256, SMEM_GEMM>>>(p_ah, p_al, p_wh + 0 * WSZ, p_wl + 0 * WSZ, eb1, p_h, NTOK, DDIM, DDIM);
    ln_kernel<<<NTOK, 256>>>(p_h, eg1, ebe1, nullptr, p_ah, p_al, nullptr);
    mma_gemm<true ><<<gD, 256, SMEM_GEMM>>>(p_ah, p_al, p_wh + 1 * WSZ, p_wl + 1 * WSZ, eb2, p_h, NTOK, DDIM, DDIM);
    ln_kernel<<<NTOK, 256>>>(p_h, eg2, ebe2, p_z, p_ah, p_al, p_zz);

    // quantizer
    mma_gemm<false><<<gK, 256, SMEM_GEMM>>>(p_ah, p_al, p_cbh, p_cbl, nullptr, p_dot, NTOK, KCB, DDIM);
    quant_kernel<<<256, 256>>>(gum, lpq);
    mma_gemm<false><<<gD, 256, SMEM_GEMM>>>(p_ah, p_al, p_cbth, p_cbtl, nullptr, p_zq, NTOK, DDIM, KCB);
    sq_kernel<<<512, 256>>>();

    // decoder
    mma_gemm<true ><<<gD, 256, SMEM_GEMM>>>(p_ah, p_al, p_wh + 2 * WSZ, p_wl + 2 * WSZ, db1, p_h, NTOK, DDIM, DDIM);
    ln_kernel<<<NTOK, 256>>>(p_h, dg1, dbe1, nullptr, p_ah, p_al, nullptr);
    mma_gemm<true ><<<gD, 256, SMEM_GEMM>>>(p_ah, p_al, p_wh + 3 * WSZ, p_wl + 3 * WSZ, db2, p_h, NTOK, DDIM, DDIM);
    ln_kernel<<<NTOK, 256>>>(p_h, dg2, dbe2, out, nullptr, nullptr, nullptr);

    fin_kernel<<<1, 256>>>(lpq, out);
}

// round 6
// speedup vs baseline: 2.5988x; 1.1154x over previous
#include <cuda_runtime.h>
#include <cuda_bf16.h>
#include <cstdint>
#include <cstddef>

#define NTOK 16384
#define DDIM 512
#define KCB  1024
#define NB   8

// ---------------- scratch (static device globals; no allocations) ----------
__device__ float g_h  [NTOK * DDIM];    // pre-LN MLP temp
__device__ float g_z  [NTOK * DDIM];    // encoder output (post-LN)
__device__ float g_zq [NTOK * DDIM];    // quantized
__device__ float g_dot[NTOK * KCB];     // z @ codebook^T
__device__ __align__(128) __nv_bfloat16 g_ah[NTOK * KCB];   // A-side split hi
__device__ __align__(128) __nv_bfloat16 g_al[NTOK * KCB];   // A-side split lo
__device__ __align__(128) __nv_bfloat16 g_wh[4 * DDIM * DDIM]; // transposed weights hi
__device__ __align__(128) __nv_bfloat16 g_wl[4 * DDIM * DDIM];
__device__ __align__(128) __nv_bfloat16 g_cbh [KCB * DDIM];    // codebook split
__device__ __align__(128) __nv_bfloat16 g_cbl [KCB * DDIM];
__device__ __align__(128) __nv_bfloat16 g_cbth[DDIM * KCB];    // codebook^T split
__device__ __align__(128) __nv_bfloat16 g_cbtl[DDIM * KCB];
__device__ float  g_zz [NTOK];
__device__ float  g_cc [KCB];
__device__ float  g_avgp[KCB];
__device__ double g_kldd;
__device__ double g_kldc;

// ---------------- PTX helpers ----------------------------------------------
__device__ __forceinline__ uint32_t smem_u32(const void* p) {
    uint32_t a;
    asm("{ .reg .u64 t; cvta.to.shared.u64 t, %1; cvt.u32.u64 %0, t; }"
        : "=r"(a) : "l"(p));
    return a;
}

#define CP_ASYNC16(s, g) \
    asm volatile("cp.async.cg.shared.global [%0], [%1], 16;" :: "r"(s), "l"(g))
#define CP_COMMIT() asm volatile("cp.async.commit_group;" ::: "memory")
#define CP_WAIT(n)  asm volatile("cp.async.wait_group %0;" :: "n"(n) : "memory")

#define LDSM4(r, addr) \
    asm volatile("ldmatrix.sync.aligned.m8n8.x4.shared.b16 {%0,%1,%2,%3}, [%4];" \
        : "=r"((r)[0]), "=r"((r)[1]), "=r"((r)[2]), "=r"((r)[3]) : "r"(addr) : "memory")

#define MMA_BF16(D, A, B0, B1) \
    asm volatile("mma.sync.aligned.m16n8k16.row.col.f32.bf16.bf16.f32 " \
        "{%0,%1,%2,%3}, {%4,%5,%6,%7}, {%8,%9}, {%0,%1,%2,%3};" \
        : "+f"((D)[0]), "+f"((D)[1]), "+f"((D)[2]), "+f"((D)[3]) \
        : "r"((A)[0]), "r"((A)[1]), "r"((A)[2]), "r"((A)[3]), "r"(B0), "r"(B1))

__device__ __forceinline__ uint32_t sw128(uint32_t off) {
    return off ^ ((off >> 3) & 0x70);
}

// ---------------- tile loader: 128 rows x 64 bf16 cols, SW128 swizzled ------
__device__ __forceinline__ void load_tile(uint32_t tb, const __nv_bfloat16* __restrict__ src,
                                          int r0, int k0, int K, int tid)
{
    #pragma unroll
    for (int i = 0; i < 4; i++) {
        int u = tid + (i << 8);
        int row = u >> 3, col8 = (u & 7) << 3;
        const __nv_bfloat16* gp = src + (size_t)(r0 + row) * K + k0 + col8;
        uint32_t off = (uint32_t)((row << 7) + (col8 << 1));
        CP_ASYNC16(tb + sw128(off), gp);
    }
}

// ---------------- mma.sync bf16x3 GEMM: C = (Ah+Al)@(Bh+Bl)^T ---------------
// 3-stage cp.async pipeline, register double-buffered fragments.
#define SMEM_STAGE 65536
#define SMEM_GEMM  (3 * SMEM_STAGE)

template<bool BIASRELU>
__global__ void __launch_bounds__(256, 1) mma_gemm(
    const __nv_bfloat16* __restrict__ Ah, const __nv_bfloat16* __restrict__ Al,
    const __nv_bfloat16* __restrict__ Bh, const __nv_bfloat16* __restrict__ Bl,
    const float* __restrict__ bias, float* __restrict__ C,
    int M, int N, int K)
{
    extern __shared__ char smem[];
    const int tid  = threadIdx.x;
    const int wid  = tid >> 5, lane = tid & 31;
    const int wm   = wid & 1, wn = wid >> 1;      // 2x4 warp grid: 64x32 per warp
    const uint32_t sb = smem_u32(smem);

    const int row0 = blockIdx.y << 7, col0 = blockIdx.x << 7;
    const int nk = K >> 6;

    float acc[4][4][4];
    #pragma unroll
    for (int i = 0; i < 4; i++)
        #pragma unroll
        for (int j = 0; j < 4; j++)
            #pragma unroll
            for (int r = 0; r < 4; r++) acc[i][j][r] = 0.f;

    // per-lane ldmatrix bases within a 128x64 bf16 tile (128B rows)
    const uint32_t a_row  = (uint32_t)(lane & 15);
    const uint32_t a_koff = (uint32_t)((lane >> 4) << 4);
    const uint32_t b_row  = (uint32_t)(((lane >> 4) << 3) + (lane & 7));
    const uint32_t b_koff = (uint32_t)(((lane >> 3) & 1) << 4);

    // prologue: stages 0, 1
    load_tile(sb + 0,     Ah, row0, 0, K, tid);
    load_tile(sb + 16384, Al, row0, 0, K, tid);
    load_tile(sb + 32768, Bh, col0, 0, K, tid);
    load_tile(sb + 49152, Bl, col0, 0, K, tid);
    CP_COMMIT();
    if (nk > 1) {
        load_tile(sb + SMEM_STAGE + 0,     Ah, row0, 64, K, tid);
        load_tile(sb + SMEM_STAGE + 16384, Al, row0, 64, K, tid);
        load_tile(sb + SMEM_STAGE + 32768, Bh, col0, 64, K, tid);
        load_tile(sb + SMEM_STAGE + 49152, Bl, col0, 64, K, tid);
        CP_COMMIT();
    }

    uint32_t ah[2][4][4], al[2][4][4], bh[2][2][4], bl[2][2][4];

    int buf = 0;
    for (int kt = 0; kt < nk; kt++) {
        if (kt + 1 < nk) CP_WAIT(1); else CP_WAIT(0);
        __syncthreads();

        // issue loads for stage kt+2 (buffer freed by the sync above)
        if (kt + 2 < nk) {
            const int k0 = (kt + 2) << 6;
            int nbuf = buf + 2; if (nbuf >= 3) nbuf -= 3;
            const uint32_t st = sb + nbuf * SMEM_STAGE;
            load_tile(st + 0,     Ah, row0, k0, K, tid);
            load_tile(st + 16384, Al, row0, k0, K, tid);
            load_tile(st + 32768, Bh, col0, k0, K, tid);
            load_tile(st + 49152, Bl, col0, k0, K, tid);
            CP_COMMIT();
        }

        const uint32_t stA_h = sb + buf * SMEM_STAGE;
        const uint32_t stA_l = stA_h + 16384;
        const uint32_t stB_h = stA_h + 32768;
        const uint32_t stB_l = stA_h + 49152;

        // prefetch fragments for ks = 0
        {
            const uint32_t k0b = 0;
            #pragma unroll
            for (int mt = 0; mt < 4; mt++) {
                uint32_t off = ((uint32_t)(wm * 64 + mt * 16) + a_row) * 128 + k0b + a_koff;
                uint32_t s = sw128(off);
                LDSM4(ah[0][mt], stA_h + s);
                LDSM4(al[0][mt], stA_l + s);
            }
            #pragma unroll
            for (int np = 0; np < 2; np++) {
                uint32_t off = ((uint32_t)(wn * 32 + np * 16) + b_row) * 128 + k0b + b_koff;
                uint32_t s = sw128(off);
                LDSM4(bh[0][np], stB_h + s);
                LDSM4(bl[0][np], stB_l + s);
            }
        }

        #pragma unroll
        for (int ks = 0; ks < 4; ks++) {
            const int cur = ks & 1, nxt = cur ^ 1;
            if (ks < 3) {
                const uint32_t k0b = (uint32_t)((ks + 1) << 5);
                #pragma unroll
                for (int mt = 0; mt < 4; mt++) {
                    uint32_t off = ((uint32_t)(wm * 64 + mt * 16) + a_row) * 128 + k0b + a_koff;
                    uint32_t s = sw128(off);
                    LDSM4(ah[nxt][mt], stA_h + s);
                    LDSM4(al[nxt][mt], stA_l + s);
                }
                #pragma unroll
                for (int np = 0; np < 2; np++) {
                    uint32_t off = ((uint32_t)(wn * 32 + np * 16) + b_row) * 128 + k0b + b_koff;
                    uint32_t s = sw128(off);
                    LDSM4(bh[nxt][np], stB_h + s);
                    LDSM4(bl[nxt][np], stB_l + s);
                }
            }
            #pragma unroll
            for (int mt = 0; mt < 4; mt++) {
                #pragma unroll
                for (int nt = 0; nt < 4; nt++) {
                    const int np = nt >> 1, pr = (nt & 1) << 1;
                    MMA_BF16(acc[mt][nt], ah[cur][mt], bh[cur][np][pr], bh[cur][np][pr + 1]);
                    MMA_BF16(acc[mt][nt], ah[cur][mt], bl[cur][np][pr], bl[cur][np][pr + 1]);
                    MMA_BF16(acc[mt][nt], al[cur][mt], bh[cur][np][pr], bh[cur][np][pr + 1]);
                }
            }
        }
        if (++buf == 3) buf = 0;
    }

    // epilogue
    const int erow = row0 + wm * 64 + (lane >> 2);
    const int ecol = col0 + wn * 32 + ((lane & 3) << 1);
    #pragma unroll
    for (int mt = 0; mt < 4; mt++) {
        #pragma unroll
        for (int nt = 0; nt < 4; nt++) {
            const int r0 = erow + mt * 16;
            const int c  = ecol + nt * 8;
            float v0 = acc[mt][nt][0], v1 = acc[mt][nt][1];
            float v2 = acc[mt][nt][2], v3 = acc[mt][nt][3];
            if (BIASRELU) {
                float b0 = bias[c], b1 = bias[c + 1];
                v0 = fmaxf(v0 + b0, 0.f); v1 = fmaxf(v1 + b1, 0.f);
                v2 = fmaxf(v2 + b0, 0.f); v3 = fmaxf(v3 + b1, 0.f);
            }
            *reinterpret_cast<float2*>(C + (size_t)r0 * N + c)       = make_float2(v0, v1);
            *reinterpret_cast<float2*>(C + (size_t)(r0 + 8) * N + c) = make_float2(v2, v3);
        }
    }
}

// ---------------- fused prep: weight/cb transposes+splits, x split, norms ----
// block ranges:
//   [0,1024)    : tsp of 4 weights (256 blocks each)
//   [1024,1536) : tsp of codebook -> cbT
//   [1536,2048) : split of codebook (grid-stride)
//   [2048,4096) : split of x (grid-stride)
//   [4096,4128) : codebook row norms + zero accumulators
__global__ void __launch_bounds__(256) prep_kernel(
    const float* __restrict__ x,
    const float* __restrict__ ew1, const float* __restrict__ ew2,
    const float* __restrict__ dw1, const float* __restrict__ dw2,
    const float* __restrict__ cb)
{
    __shared__ float t[32][33];
    const int blk = blockIdx.x, tid = threadIdx.x;

    if (blk < 1536) {
        // transpose + split
        const float* in; __nv_bfloat16 *oh, *ol; int R, C, bx, by;
        if (blk < 1024) {
            int w = blk >> 8, idx = blk & 255;
            const float* ws[4] = {ew1, ew2, dw1, dw2};
            in = ws[w];
            oh = g_wh + (size_t)w * DDIM * DDIM;
            ol = g_wl + (size_t)w * DDIM * DDIM;
            R = DDIM; C = DDIM; bx = idx & 15; by = idx >> 4;
        } else {
            int idx = blk - 1024;
            in = cb; oh = g_cbth; ol = g_cbtl;
            R = KCB; C = DDIM; bx = idx & 15; by = idx >> 4;
        }
        const int txx = tid & 31, tyy = tid >> 5;
        #pragma unroll
        for (int i = tyy; i < 32; i += 8)
            t[i][txx] = in[(size_t)(by * 32 + i) * C + bx * 32 + txx];
        __syncthreads();
        #pragma unroll
        for (int i = tyy; i < 32; i += 8) {
            float v = t[txx][i];
            size_t o = (size_t)(bx * 32 + i) * R + by * 32 + txx;
            __nv_bfloat16 h = __float2bfloat16(v);
            oh[o] = h;
            ol[o] = __float2bfloat16(v - __bfloat162float(h));
        }
    } else if (blk < 2048) {
        int lb = blk - 1536;
        const int n = KCB * DDIM;
        for (int i = lb * 256 + tid; i < n; i += 512 * 256) {
            float v = cb[i];
            __nv_bfloat16 h = __float2bfloat16(v);
            g_cbh[i] = h;
            g_cbl[i] = __float2bfloat16(v - __bfloat162float(h));
        }
    } else if (blk < 4096) {
        int lb = blk - 2048;
        const int n = NTOK * DDIM;
        for (int i = lb * 256 + tid; i < n; i += 2048 * 256) {
            float v = x[i];
            __nv_bfloat16 h = __float2bfloat16(v);
            g_ah[i] = h;
            g_al[i] = __float2bfloat16(v - __bfloat162float(h));
        }
    } else {
        int lb = blk - 4096;
        int lane = tid & 31, wrp = tid >> 5;
        int gw = lb * 8 + wrp;                    // 256 warps
        for (int r = gw; r < KCB; r += 256) {
            const float* p = cb + (size_t)r * DDIM;
            float s = 0.f;
            for (int i = lane; i < DDIM; i += 32) { float v = p[i]; s += v * v; }
            #pragma unroll
            for (int o = 16; o; o >>= 1) s += __shfl_xor_sync(0xffffffffu, s, o);
            if (!lane) g_cc[r] = s;
        }
        int g = lb * 256 + tid;
        if (g < KCB) g_avgp[g] = 0.f;
        if (g == 0) { g_kldd = 0.0; g_kldc = 0.0; }
    }
}

// ---------------- LayerNorm (row 512) + optional fp32 out + bf16 splits ------
__global__ void __launch_bounds__(256) ln_kernel(
    const float* __restrict__ in, const float* __restrict__ g,
    const float* __restrict__ be, float* __restrict__ out,
    __nv_bfloat16* __restrict__ oh, __nv_bfloat16* __restrict__ ol,
    float* __restrict__ zz)
{
    __shared__ float sm[8];
    const int row = blockIdx.x, tid = threadIdx.x;
    const int lane = tid & 31, wrp = tid >> 5;
    const float* p = in + (size_t)row * DDIM;
    float x0 = p[tid], x1 = p[tid + 256];

    float s = x0 + x1;
    #pragma unroll
    for (int o = 16; o; o >>= 1) s += __shfl_xor_sync(0xffffffffu, s, o);
    if (!lane) sm[wrp] = s;
    __syncthreads();
    float mean = (sm[0] + sm[1] + sm[2] + sm[3] + sm[4] + sm[5] + sm[6] + sm[7]) * (1.f / DDIM);
    __syncthreads();

    float d0 = x0 - mean, d1 = x1 - mean;
    float v = d0 * d0 + d1 * d1;
    #pragma unroll
    for (int o = 16; o; o >>= 1) v += __shfl_xor_sync(0xffffffffu, v, o);
    if (!lane) sm[wrp] = v;
    __syncthreads();
    float rstd = rsqrtf((sm[0] + sm[1] + sm[2] + sm[3] + sm[4] + sm[5] + sm[6] + sm[7]) * (1.f / DDIM) + 1e-5f);

    float y0 = d0 * rstd * g[tid]       + be[tid];
    float y1 = d1 * rstd * g[tid + 256] + be[tid + 256];
    if (out) {
        float* q = out + (size_t)row * DDIM;
        q[tid] = y0; q[tid + 256] = y1;
    }
    if (oh) {
        size_t b = (size_t)row * DDIM;
        __nv_bfloat16 h0 = __float2bfloat16(y0);
        __nv_bfloat16 h1 = __float2bfloat16(y1);
        oh[b + tid]       = h0; ol[b + tid]       = __float2bfloat16(y0 - __bfloat162float(h0));
        oh[b + tid + 256] = h1; ol[b + tid + 256] = __float2bfloat16(y1 - __bfloat162float(h1));
    }
    if (zz) {
        float q = y0 * y0 + y1 * y1;
        #pragma unroll
        for (int o = 16; o; o >>= 1) q += __shfl_xor_sync(0xffffffffu, q, o);
        __syncthreads();
        if (!lane) sm[wrp] = q;
        __syncthreads();
        if (!tid) zz[row] = sm[0] + sm[1] + sm[2] + sm[3] + sm[4] + sm[5] + sm[6] + sm[7];
    }
}

// ---------------- quantizer: writes encodings as bf16 splits -----------------
__global__ void __launch_bounds__(256) quant_kernel(
    const float* __restrict__ gum, const float* __restrict__ lpq)
{
    __shared__ float s_cc[KCB];
    __shared__ float s_avg[8][KCB];
    const int tid = threadIdx.x, lane = tid & 31, wid = tid >> 5;
    const float w = 0.5f / fmaxf(__expf(lpq[0]), 1e-10f);

    for (int j = tid; j < KCB; j += 256) s_cc[j] = g_cc[j];
    for (int j = tid; j < 8 * KCB; j += 256) (&s_avg[0][0])[j] = 0.f;
    __syncthreads();

    double kd = 0.0;
    const int row0 = blockIdx.x * 64;
    for (int r = wid; r < 64; r += 8) {
        const int row = row0 + r;
        const float* dp = g_dot + (size_t)row * KCB;
        const float* up = gum   + (size_t)row * KCB;
        const float zzr = g_zz[row];

        float lg[32];
        float mx = -1e30f;
        #pragma unroll
        for (int q = 0; q < 32; q++) {
            int j = lane + (q << 5);
            float l = w * (2.f * dp[j] - zzr - s_cc[j]);
            lg[q] = l;
            mx = fmaxf(mx, l);
        }
        #pragma unroll
        for (int o = 16; o; o >>= 1) mx = fmaxf(mx, __shfl_xor_sync(0xffffffffu, mx, o));

        float se = 0.f;
        #pragma unroll
        for (int q = 0; q < 32; q++) se += __expf(lg[q] - mx);
        #pragma unroll
        for (int o = 16; o; o >>= 1) se += __shfl_xor_sync(0xffffffffu, se, o);
        const float lse = __logf(se);

        float pd = 0.f;
        #pragma unroll
        for (int q = 0; q < 32; q++) {
            int j = lane + (q << 5);
            float lp = lg[q] - mx - lse;
            float p = __expf(lp);
            pd += p * lp;
            s_avg[wid][j] += p;
        }
        #pragma unroll
        for (int o = 16; o; o >>= 1) pd += __shfl_xor_sync(0xffffffffu, pd, o);
        if (!lane) kd += (double)pd;

        float mx2 = -1e30f;
        #pragma unroll
        for (int q = 0; q < 32; q++) {
            int j = lane + (q << 5);
            float u = up[j];
            float gn = -__logf(-__logf(u + 1e-10f) + 1e-10f);
            float a = lg[q] + gn;
            lg[q] = a;
            mx2 = fmaxf(mx2, a);
        }
        #pragma unroll
        for (int o = 16; o; o >>= 1) mx2 = fmaxf(mx2, __shfl_xor_sync(0xffffffffu, mx2, o));

        float s2 = 0.f;
        #pragma unroll
        for (int q = 0; q < 32; q++) { float e = __expf(lg[q] - mx2); lg[q] = e; s2 += e; }
        #pragma unroll
        for (int o = 16; o; o >>= 1) s2 += __shfl_xor_sync(0xffffffffu, s2, o);
        const float inv = 1.f / s2;

        __nv_bfloat16* eph = g_ah + (size_t)row * KCB;
        __nv_bfloat16* epl = g_al + (size_t)row * KCB;
        #pragma unroll
        for (int q = 0; q < 32; q++) {
            int j = lane + (q << 5);
            float e = lg[q] * inv;
            __nv_bfloat16 h = __float2bfloat16(e);
            eph[j] = h;
            epl[j] = __float2bfloat16(e - __bfloat162float(h));
        }
    }
    __syncthreads();

    for (int j = tid; j < KCB; j += 256) {
        float s = 0.f;
        #pragma unroll
        for (int ww = 0; ww < 8; ww++) s += s_avg[ww][j];
        atomicAdd(&g_avgp[j], s);
    }
    if (!lane) atomicAdd(&g_kldd, kd);
}

// ---------------- sum((z - z_q)^2) + split z_q for decoder -------------------
__global__ void __launch_bounds__(256) sq_kernel()
{
    size_t gid = (size_t)blockIdx.x * 256 + threadIdx.x;
    size_t stride = (size_t)gridDim.x * 256;
    float acc = 0.f;
    for (size_t i = gid; i < (size_t)NTOK * DDIM; i += stride) {
        float qv = g_zq[i];
        float d = g_z[i] - qv;
        acc += d * d;
        __nv_bfloat16 h = __float2bfloat16(qv);
        g_ah[i] = h;
        g_al[i] = __float2bfloat16(qv - __bfloat162float(h));
    }
    #pragma unroll
    for (int o = 16; o; o >>= 1) acc += __shfl_xor_sync(0xffffffffu, acc, o);
    __shared__ double sred[8];
    int lane = threadIdx.x & 31, wid = threadIdx.x >> 5;
    if (!lane) sred[wid] = (double)acc;
    __syncthreads();
    if (threadIdx.x == 0) {
        double s = 0.0;
        #pragma unroll
        for (int i = 0; i < 8; i++) s += sred[i];
        atomicAdd(&g_kldc, s);
    }
}

// ---------------- finalize ----------------------------------------------------
__global__ void __launch_bounds__(256) fin_kernel(
    const float* __restrict__ lpq, float* __restrict__ out)
{
    __shared__ double red[256];
    const int tid = threadIdx.x;
    double h = 0.0;
    for (int j = tid; j < KCB; j += 256) {
        float a = g_avgp[j] * (1.f / NTOK);
        h += (double)(a * __logf(a + 1e-7f));
    }
    red[tid] = h; __syncthreads();
    #pragma unroll
    for (int o = 128; o; o >>= 1) { if (tid < o) red[tid] += red[tid + o]; __syncthreads(); }
    if (!tid) {
        float w = 0.5f / fmaxf(__expf(lpq[0]), 1e-10f);
        double loss = g_kldd / (double)NB + g_kldc * (double)w / (double)NB;
        out[(size_t)NTOK * DDIM]     = (float)loss;
        out[(size_t)NTOK * DDIM + 1] = __expf((float)(-red[0]));
    }
}

// ---------------- launch ------------------------------------------------------
extern "C" void kernel_launch(void* const* d_in, const int* in_sizes, int n_in,
                              void* d_out, int out_size)
{
    (void)in_sizes; (void)n_in; (void)out_size;
    const float* x    = (const float*)d_in[0];
    const float* gum  = (const float*)d_in[1];
    const float* ew1  = (const float*)d_in[2];  const float* eb1  = (const float*)d_in[3];
    const float* eg1  = (const float*)d_in[4];  const float* ebe1 = (const float*)d_in[5];
    const float* ew2  = (const float*)d_in[6];  const float* eb2  = (const float*)d_in[7];
    const float* eg2  = (const float*)d_in[8];  const float* ebe2 = (const float*)d_in[9];
    const float* dw1  = (const float*)d_in[10]; const float* db1  = (const float*)d_in[11];
    const float* dg1  = (const float*)d_in[12]; const float* dbe1 = (const float*)d_in[13];
    const float* dw2  = (const float*)d_in[14]; const float* db2  = (const float*)d_in[15];
    const float* dg2  = (const float*)d_in[16]; const float* dbe2 = (const float*)d_in[17];
    const float* cb   = (const float*)d_in[18];
    const float* lpq  = (const float*)d_in[19];
    float* out = (float*)d_out;

    float *p_h, *p_z, *p_zq, *p_dot, *p_zz;
    __nv_bfloat16 *p_ah, *p_al, *p_wh, *p_wl, *p_cbh, *p_cbl, *p_cbth, *p_cbtl;
    cudaGetSymbolAddress((void**)&p_h,    g_h);
    cudaGetSymbolAddress((void**)&p_z,    g_z);
    cudaGetSymbolAddress((void**)&p_zq,   g_zq);
    cudaGetSymbolAddress((void**)&p_dot,  g_dot);
    cudaGetSymbolAddress((void**)&p_zz,   g_zz);
    cudaGetSymbolAddress((void**)&p_ah,   g_ah);
    cudaGetSymbolAddress((void**)&p_al,   g_al);
    cudaGetSymbolAddress((void**)&p_wh,   g_wh);
    cudaGetSymbolAddress((void**)&p_wl,   g_wl);
    cudaGetSymbolAddress((void**)&p_cbh,  g_cbh);
    cudaGetSymbolAddress((void**)&p_cbl,  g_cbl);
    cudaGetSymbolAddress((void**)&p_cbth, g_cbth);
    cudaGetSymbolAddress((void**)&p_cbtl, g_cbtl);

    cudaFuncSetAttribute(mma_gemm<true>,  cudaFuncAttributeMaxDynamicSharedMemorySize, SMEM_GEMM);
    cudaFuncSetAttribute(mma_gemm<false>, cudaFuncAttributeMaxDynamicSharedMemorySize, SMEM_GEMM);

    const int WSZ = DDIM * DDIM;
    dim3 gD(DDIM / 128, NTOK / 128);   // (4, 128)
    dim3 gK(KCB  / 128, NTOK / 128);   // (8, 128)

    // 1: fused prep
    prep_kernel<<<4128, 256>>>(x, ew1, ew2, dw1, dw2, cb);

    // 2-5: encoder
    mma_gemm<true ><<<gD, 256, SMEM_GEMM>>>(p_ah, p_al, p_wh + 0 * WSZ, p_wl + 0 * WSZ, eb1, p_h, NTOK, DDIM, DDIM);
    ln_kernel<<<NTOK, 256>>>(p_h, eg1, ebe1, nullptr, p_ah, p_al, nullptr);
    mma_gemm<true ><<<gD, 256, SMEM_GEMM>>>(p_ah, p_al, p_wh + 1 * WSZ, p_wl + 1 * WSZ, eb2, p_h, NTOK, DDIM, DDIM);
    ln_kernel<<<NTOK, 256>>>(p_h, eg2, ebe2, p_z, p_ah, p_al, p_zz);

    // 6: quantizer logits GEMM  (launch #6 -> ncu -s 5 profiles this)
    mma_gemm<false><<<gK, 256, SMEM_GEMM>>>(p_ah, p_al, p_cbh, p_cbl, nullptr, p_dot, NTOK, KCB, DDIM);
    quant_kernel<<<256, 256>>>(gum, lpq);
    mma_gemm<false><<<gD, 256, SMEM_GEMM>>>(p_ah, p_al, p_cbth, p_cbtl, nullptr, p_zq, NTOK, DDIM, KCB);
    sq_kernel<<<512, 256>>>();

    // decoder
    mma_gemm<true ><<<gD, 256, SMEM_GEMM>>>(p_ah, p_al, p_wh + 2 * WSZ, p_wl + 2 * WSZ, db1, p_h, NTOK, DDIM, DDIM);
    ln_kernel<<<NTOK, 256>>>(p_h, dg1, dbe1, nullptr, p_ah, p_al, nullptr);
    mma_gemm<true ><<<gD, 256, SMEM_GEMM>>>(p_ah, p_al, p_wh + 3 * WSZ, p_wl + 3 * WSZ, db2, p_h, NTOK, DDIM, DDIM);
    ln_kernel<<<NTOK, 256>>>(p_h, dg2, dbe2, out, nullptr, nullptr, nullptr);

    fin_kernel<<<1, 256>>>(lpq, out);
}